// round 3
// baseline (speedup 1.0000x reference)
#include <cuda_runtime.h>

#define NHEADS  20
#define NUM_EX  13

// Folded/duplicated weight buffer layout (float offsets)
#define OFF_E     0                    // E'   : 20*13*12 = 3120 (b1 + emb@W1e + bf@W1f folded)
#define OFF_W1FD  3120                 // W1fD : 20*3*20  = 1200 (each value duplicated {w,w})
#define OFF_W2D   4320                 // W2D  : 20*20    = 400  (duplicated)
#define OFF_B2D   4720                 // b2D  : 20*2     = 40   (duplicated)
#define OFF_WO    4760                 // Wo   : 20
#define OFF_BO    4780                 // bo   : 1
#define PREP_N    4781
#define PREP_CAP  4784

__device__ float g_prep[PREP_CAP];

typedef unsigned long long u64;

// ---------------- packed f32x2 helpers (sm_100+) ----------------
__device__ __forceinline__ u64 pk2(float lo, float hi) {
    u64 r; asm("mov.b64 %0, {%1, %2};" : "=l"(r) : "f"(lo), "f"(hi)); return r;
}
__device__ __forceinline__ void upk2(float& lo, float& hi, u64 v) {
    asm("mov.b64 {%0, %1}, %2;" : "=f"(lo), "=f"(hi) : "l"(v));
}
#define FMA2(d, a, b, c) asm("fma.rn.f32x2 %0, %1, %2, %3;" : "=l"(d) : "l"(a), "l"(b), "l"(c))
#define MUL2(d, a, b)    asm("mul.rn.f32x2 %0, %1, %2;"     : "=l"(d) : "l"(a), "l"(b))
#define AND64(d, a, m)   asm("and.b64 %0, %1, %2;"          : "=l"(d) : "l"(a), "l"(m))

// ---------------------------------------------------------------------------
// Prep: fold Wf/bf/emb/b1 into tables; duplicate uniform weights into pairs.
// ---------------------------------------------------------------------------
__global__ void prep_kernel(const float* __restrict__ emb, const float* __restrict__ Wf,
                            const float* __restrict__ bf,  const float* __restrict__ W1,
                            const float* __restrict__ b1,  const float* __restrict__ W2,
                            const float* __restrict__ b2,  const float* __restrict__ Wo,
                            const float* __restrict__ bo) {
    int t = blockIdx.x * blockDim.x + threadIdx.x;
    if (t >= PREP_N) return;
    float v = 0.0f;
    if (t < OFF_W1FD) {
        // E'[h][idx][j] = b1 + emb@W1e + bf@W1f (rows padded to 12)
        int j = t % 12; int r = t / 12; int idx = r % NUM_EX; int h = r / NUM_EX;
        if (j < 10) {
            v = b1[h * 10 + j];
            #pragma unroll
            for (int c = 0; c < 3; c++) v += emb[idx * 3 + c] * W1[(h * 8 + c) * 10 + j];
            #pragma unroll
            for (int i = 0; i < 5; i++) v += bf[i] * W1[(h * 8 + 3 + i) * 10 + j];
        }
    } else if (t < OFF_W2D) {
        // W1fD[h][c][2j(+1)] = sum_i Wf[c][i]*W1[h][3+i][j]   (duplicated)
        int u = t - OFF_W1FD; int jd = u % 20; int j = jd >> 1;
        int r = u / 20; int c = r % 3; int h = r / 3;
        #pragma unroll
        for (int i = 0; i < 5; i++) v += Wf[c * 5 + i] * W1[(h * 8 + 3 + i) * 10 + j];
    } else if (t < OFF_B2D) {
        int u = t - OFF_W2D; int j = (u % 20) >> 1; int h = u / 20;
        v = W2[h * 10 + j];
    } else if (t < OFF_WO) {
        int u = t - OFF_B2D; v = b2[u >> 1];
    } else if (t < OFF_BO) {
        v = Wo[t - OFF_WO];
    } else {
        v = bo[0];
    }
    g_prep[t] = v;
}

__device__ __forceinline__ float softplus_f(float x) {
    float m = fmaxf(x, 0.0f);
    float z = __expf(-fabsf(x));
    return m + __logf(1.0f + z);
}

// ---------------------------------------------------------------------------
// Main kernel: 2 samples/thread, packed f32x2 math, duplicated weights in smem.
// ---------------------------------------------------------------------------
__global__ __launch_bounds__(256, 2) void airfit_kernel(const int* __restrict__ e,
                                                        const float* __restrict__ f,
                                                        float* __restrict__ out, int B) {
    __shared__ __align__(16) float sp[PREP_CAP];
    for (int i = threadIdx.x; i < PREP_N; i += 256) sp[i] = g_prep[i];
    __syncthreads();

    int s0 = blockIdx.x * 512 + threadIdx.x;
    if (s0 >= B) return;
    int s1 = s0 + 256;
    int s1c = (s1 < B) ? s1 : s0;   // clamp loads; store guarded at end

    const float4* fA4 = reinterpret_cast<const float4*>(f) + (size_t)s0  * 15;
    const float4* fB4 = reinterpret_cast<const float4*>(f) + (size_t)s1c * 15;
    const int4*   eA4 = reinterpret_cast<const int4*>(e)   + (size_t)s0  * 5;
    const int4*   eB4 = reinterpret_cast<const int4*>(e)   + (size_t)s1c * 5;

    const u64 ABSM  = 0x7FFFFFFF7FFFFFFFULL;
    const u64 K0505 = pk2(0.505f, 0.505f);
    const u64 K0495 = pk2(0.495f, 0.495f);

    float res0 = sp[OFF_BO], res1 = res0;

    #pragma unroll
    for (int hg = 0; hg < 5; hg++) {
        // f rows (12 floats per 4-head group) for both samples, packed as pairs
        float4 a0 = fA4[hg * 3 + 0], a1 = fA4[hg * 3 + 1], a2v = fA4[hg * 3 + 2];
        float4 b0 = fB4[hg * 3 + 0], b1v = fB4[hg * 3 + 1], b2v = fB4[hg * 3 + 2];
        u64 g2[12];
        g2[0] = pk2(a0.x, b0.x);  g2[1] = pk2(a0.y, b0.y);
        g2[2] = pk2(a0.z, b0.z);  g2[3] = pk2(a0.w, b0.w);
        g2[4] = pk2(a1.x, b1v.x); g2[5] = pk2(a1.y, b1v.y);
        g2[6] = pk2(a1.z, b1v.z); g2[7] = pk2(a1.w, b1v.w);
        g2[8] = pk2(a2v.x, b2v.x); g2[9] = pk2(a2v.y, b2v.y);
        g2[10] = pk2(a2v.z, b2v.z); g2[11] = pk2(a2v.w, b2v.w);

        int4 i0 = eA4[hg], i1 = eB4[hg];
        int ix0[4] = {i0.x, i0.y, i0.z, i0.w};
        int ix1[4] = {i1.x, i1.y, i1.z, i1.w};

        #pragma unroll
        for (int k = 0; k < 4; k++) {
            int h = hg * 4 + k;

            // accumulator init = packed E' rows (per-sample embedding lookup)
            const float* Er0 = &sp[OFF_E + (h * NUM_EX + ix0[k]) * 12];
            const float* Er1 = &sp[OFF_E + (h * NUM_EX + ix1[k]) * 12];
            float4 x0 = *reinterpret_cast<const float4*>(Er0);
            float4 x1 = *reinterpret_cast<const float4*>(Er0 + 4);
            float2 x2 = *reinterpret_cast<const float2*>(Er0 + 8);
            float4 y0 = *reinterpret_cast<const float4*>(Er1);
            float4 y1 = *reinterpret_cast<const float4*>(Er1 + 4);
            float2 y2 = *reinterpret_cast<const float2*>(Er1 + 8);
            u64 acc[10];
            acc[0] = pk2(x0.x, y0.x); acc[1] = pk2(x0.y, y0.y);
            acc[2] = pk2(x0.z, y0.z); acc[3] = pk2(x0.w, y0.w);
            acc[4] = pk2(x1.x, y1.x); acc[5] = pk2(x1.y, y1.y);
            acc[6] = pk2(x1.z, y1.z); acc[7] = pk2(x1.w, y1.w);
            acc[8] = pk2(x2.x, y2.x); acc[9] = pk2(x2.y, y2.y);

            // + f(3) @ W1f(3x10), packed; weights pre-duplicated in smem
            #pragma unroll
            for (int c = 0; c < 3; c++) {
                const ulonglong2* wr = reinterpret_cast<const ulonglong2*>(
                    &sp[OFF_W1FD + (h * 3 + c) * 20]);
                u64 fv = g2[k * 3 + c];
                ulonglong2 w01 = wr[0], w23 = wr[1], w45 = wr[2], w67 = wr[3], w89 = wr[4];
                FMA2(acc[0], fv, w01.x, acc[0]); FMA2(acc[1], fv, w01.y, acc[1]);
                FMA2(acc[2], fv, w23.x, acc[2]); FMA2(acc[3], fv, w23.y, acc[3]);
                FMA2(acc[4], fv, w45.x, acc[4]); FMA2(acc[5], fv, w45.y, acc[5]);
                FMA2(acc[6], fv, w67.x, acc[6]); FMA2(acc[7], fv, w67.y, acc[7]);
                FMA2(acc[8], fv, w89.x, acc[8]); FMA2(acc[9], fv, w89.y, acc[9]);
            }

            // packed leaky_relu: leaky(a) = 0.505*a + 0.495*|a|, then dot with W2
            u64 d2 = *reinterpret_cast<const u64*>(&sp[OFF_B2D + h * 2]);
            const ulonglong2* ur = reinterpret_cast<const ulonglong2*>(&sp[OFF_W2D + h * 20]);
            ulonglong2 u01 = ur[0], u23 = ur[1], u45 = ur[2], u67 = ur[3], u89 = ur[4];
            u64 w2p[10] = {u01.x, u01.y, u23.x, u23.y, u45.x, u45.y, u67.x, u67.y, u89.x, u89.y};
            #pragma unroll
            for (int j = 0; j < 10; j++) {
                u64 ab, t1, t2;
                AND64(ab, acc[j], ABSM);
                MUL2(t1, ab, K0495);
                FMA2(t2, acc[j], K0505, t1);
                FMA2(d2, t2, w2p[j], d2);
            }

            // scalar softplus per half + output projection
            float dl, dh; upk2(dl, dh, d2);
            float woh = sp[OFF_WO + h];
            res0 = fmaf(softplus_f(dl), woh, res0);
            res1 = fmaf(softplus_f(dh), woh, res1);
        }
    }

    out[s0] = res0;
    if (s1 < B) out[s1] = res1;
}

// ---------------------------------------------------------------------------
extern "C" void kernel_launch(void* const* d_in, const int* in_sizes, int n_in,
                              void* d_out, int out_size) {
    const int*   e   = (const int*)  d_in[0];
    const float* f   = (const float*)d_in[1];
    const float* emb = (const float*)d_in[2];
    const float* Wf  = (const float*)d_in[3];
    const float* bf  = (const float*)d_in[4];
    const float* W1  = (const float*)d_in[5];
    const float* b1  = (const float*)d_in[6];
    const float* W2  = (const float*)d_in[7];
    const float* b2  = (const float*)d_in[8];
    const float* Wo  = (const float*)d_in[9];
    const float* bo  = (const float*)d_in[10];
    float* out = (float*)d_out;
    int B = out_size;

    prep_kernel<<<(PREP_N + 255) / 256, 256>>>(emb, Wf, bf, W1, b1, W2, b2, Wo, bo);
    airfit_kernel<<<(B + 511) / 512, 256>>>(e, f, out, B);
}

// round 4
// speedup vs baseline: 1.2103x; 1.2103x over previous
#include <cuda_runtime.h>

#define NHEADS  20
#define NUM_EX  13

// E' table (per-sample indexed) -> shared memory: [h][idx][12] = 3120 floats
#define E_SIZE   3120
// Uniform weight blob -> __constant__: per head 64 floats:
//   [0..11]  W1f c=0 (10 + pad)     [12..23] W1f c=1      [24..35] W1f c=2
//   [36..47] w2a = 0.505*W2 (10+pad) [48..59] w2b = 0.495*W2
//   [60] b2   [61] Wo   [62,63] pad
// plus [1280] = bo
#define W_SIZE   1281
#define PREP_N   (E_SIZE + W_SIZE)

__device__ float g_e[E_SIZE];
__device__ float g_w[W_SIZE + 3];
__constant__ float c_w[W_SIZE + 3];

// ---------------------------------------------------------------------------
// Prep: fold Wf/bf/emb/b1 into E'; fold leaky slopes into W2; build blobs.
// ---------------------------------------------------------------------------
__global__ void prep_kernel(const float* __restrict__ emb, const float* __restrict__ Wf,
                            const float* __restrict__ bf,  const float* __restrict__ W1,
                            const float* __restrict__ b1,  const float* __restrict__ W2,
                            const float* __restrict__ b2,  const float* __restrict__ Wo,
                            const float* __restrict__ bo) {
    int t = blockIdx.x * blockDim.x + threadIdx.x;
    if (t >= PREP_N) return;
    if (t < E_SIZE) {
        // E'[h][idx][j] = b1[h][j] + sum_c emb[idx][c]*W1[h][c][j] + sum_i bf[i]*W1[h][3+i][j]
        int j = t % 12; int r = t / 12; int idx = r % NUM_EX; int h = r / NUM_EX;
        float v = 0.0f;
        if (j < 10) {
            v = b1[h * 10 + j];
            #pragma unroll
            for (int c = 0; c < 3; c++) v += emb[idx * 3 + c] * W1[(h * 8 + c) * 10 + j];
            #pragma unroll
            for (int i = 0; i < 5; i++) v += bf[i] * W1[(h * 8 + 3 + i) * 10 + j];
        }
        g_e[t] = v;
        return;
    }
    int u = t - E_SIZE;
    float v = 0.0f;
    if (u < 1280) {
        int h = u / 64; int o = u % 64;
        if (o < 36) {                       // W1f[h][c][j] = sum_i Wf[c][i]*W1[h][3+i][j]
            int c = o / 12; int j = o % 12;
            if (j < 10) {
                #pragma unroll
                for (int i = 0; i < 5; i++) v += Wf[c * 5 + i] * W1[(h * 8 + 3 + i) * 10 + j];
            }
        } else if (o < 48) {                // w2a = 0.505 * W2
            int j = o - 36; if (j < 10) v = 0.505f * W2[h * 10 + j];
        } else if (o < 60) {                // w2b = 0.495 * W2
            int j = o - 48; if (j < 10) v = 0.495f * W2[h * 10 + j];
        } else if (o == 60) {
            v = b2[h];
        } else if (o == 61) {
            v = Wo[h];
        }
    } else {
        v = bo[0];                          // u == 1280
    }
    g_w[u] = v;
}

__device__ __forceinline__ float fabs_bits(float x) {
    return __int_as_float(__float_as_int(x) & 0x7FFFFFFF);   // LOP3 on alu pipe
}

// ---------------------------------------------------------------------------
// Main: 1 sample/thread. E' from smem (indexed), all uniform weights from
// __constant__ (LDCU / uniform port -> zero L1 traffic, UR operands).
// ---------------------------------------------------------------------------
__global__ __launch_bounds__(256) void airfit_kernel(const int* __restrict__ e,
                                                     const float* __restrict__ f,
                                                     float* __restrict__ out, int B) {
    __shared__ __align__(16) float sE[E_SIZE];
    for (int i = threadIdx.x; i < E_SIZE; i += 256) sE[i] = g_e[i];
    __syncthreads();

    int s = blockIdx.x * 256 + threadIdx.x;
    if (s >= B) return;

    const float4* f4 = reinterpret_cast<const float4*>(f) + (size_t)s * 15;
    const int4*   e4 = reinterpret_cast<const int4*>(e)   + (size_t)s * 5;

    float res = c_w[1280];

    #pragma unroll
    for (int hg = 0; hg < 5; hg++) {
        float4 fA = f4[hg * 3 + 0];
        float4 fB = f4[hg * 3 + 1];
        float4 fC = f4[hg * 3 + 2];
        int4   ev = e4[hg];
        float g[12] = {fA.x, fA.y, fA.z, fA.w, fB.x, fB.y, fB.z, fB.w,
                       fC.x, fC.y, fC.z, fC.w};
        int idx[4] = {ev.x, ev.y, ev.z, ev.w};

        #pragma unroll
        for (int k = 0; k < 4; k++) {
            const int h = hg * 4 + k;
            const int wb = h * 64;                      // constant blob base (literal)

            // accumulator init = E'[h][e] row from smem
            const float* Er = &sE[(h * NUM_EX + idx[k]) * 12];
            float4 A0 = *reinterpret_cast<const float4*>(Er);
            float4 A1 = *reinterpret_cast<const float4*>(Er + 4);
            float2 A2 = *reinterpret_cast<const float2*>(Er + 8);
            float a[10] = {A0.x, A0.y, A0.z, A0.w, A1.x, A1.y, A1.z, A1.w, A2.x, A2.y};

            // + f(3) @ W1f(3x10), weights from constant (uniform port)
            #pragma unroll
            for (int c = 0; c < 3; c++) {
                float fv = g[k * 3 + c];
                #pragma unroll
                for (int j = 0; j < 10; j++)
                    a[j] = fmaf(fv, c_w[wb + c * 12 + j], a[j]);
            }

            // leaky folded: d = b2 + sum a_j*w2a_j + |a_j|*w2b_j
            float d = c_w[wb + 60];
            #pragma unroll
            for (int j = 0; j < 10; j++) {
                d = fmaf(a[j],          c_w[wb + 36 + j], d);
                d = fmaf(fabs_bits(a[j]), c_w[wb + 48 + j], d);
            }

            // softplus(d) = max(d,0) + log(1+exp(-|d|))
            float m = fmaxf(d, 0.0f);
            float z = __expf(-fabsf(d));
            float spv = m + __logf(1.0f + z);

            res = fmaf(spv, c_w[wb + 61], res);
        }
    }
    out[s] = res;
}

// ---------------------------------------------------------------------------
extern "C" void kernel_launch(void* const* d_in, const int* in_sizes, int n_in,
                              void* d_out, int out_size) {
    const int*   e   = (const int*)  d_in[0];
    const float* f   = (const float*)d_in[1];
    const float* emb = (const float*)d_in[2];
    const float* Wf  = (const float*)d_in[3];
    const float* bf  = (const float*)d_in[4];
    const float* W1  = (const float*)d_in[5];
    const float* b1  = (const float*)d_in[6];
    const float* W2  = (const float*)d_in[7];
    const float* b2  = (const float*)d_in[8];
    const float* Wo  = (const float*)d_in[9];
    const float* bo  = (const float*)d_in[10];
    float* out = (float*)d_out;
    int B = out_size;

    prep_kernel<<<(PREP_N + 255) / 256, 256>>>(emb, Wf, bf, W1, b1, W2, b2, Wo, bo);

    // push folded uniform weights into constant bank (D2D copy, graph-capturable)
    void* c_addr = nullptr;
    void* g_addr = nullptr;
    cudaGetSymbolAddress(&c_addr, c_w);
    cudaGetSymbolAddress(&g_addr, g_w);
    cudaMemcpyAsync(c_addr, g_addr, W_SIZE * sizeof(float), cudaMemcpyDeviceToDevice);

    airfit_kernel<<<(B + 255) / 256, 256>>>(e, f, out, B);
}

// round 5
// speedup vs baseline: 1.2473x; 1.0306x over previous
#include <cuda_runtime.h>

#define NHEADS  20
#define NUM_EX  13

// E' table (per-sample indexed) -> shared memory: [h][idx][12] = 3120 floats
#define E_SIZE   3120
// Uniform weight blob -> __constant__: per head 64 floats:
//   [0..11]  W1f c=0 (10 + pad)     [12..23] W1f c=1      [24..35] W1f c=2
//   [36..47] w2a = 0.505*W2 (10+pad) [48..59] w2b = 0.495*W2
//   [60] b2   [61] Wo   [62,63] pad
// plus [1280] = bo
#define W_SIZE   1281
#define PREP_N   (E_SIZE + W_SIZE)

__device__ float g_e[E_SIZE];
__device__ float g_w[W_SIZE + 3];
__constant__ float c_w[W_SIZE + 3];

// ---------------------------------------------------------------------------
// Prep: fold Wf/bf/emb/b1 into E'; fold leaky slopes into W2; build blobs.
// ---------------------------------------------------------------------------
__global__ void prep_kernel(const float* __restrict__ emb, const float* __restrict__ Wf,
                            const float* __restrict__ bf,  const float* __restrict__ W1,
                            const float* __restrict__ b1,  const float* __restrict__ W2,
                            const float* __restrict__ b2,  const float* __restrict__ Wo,
                            const float* __restrict__ bo) {
    int t = blockIdx.x * blockDim.x + threadIdx.x;
    if (t >= PREP_N) return;
    if (t < E_SIZE) {
        // E'[h][idx][j] = b1[h][j] + sum_c emb[idx][c]*W1[h][c][j] + sum_i bf[i]*W1[h][3+i][j]
        int j = t % 12; int r = t / 12; int idx = r % NUM_EX; int h = r / NUM_EX;
        float v = 0.0f;
        if (j < 10) {
            v = b1[h * 10 + j];
            #pragma unroll
            for (int c = 0; c < 3; c++) v += emb[idx * 3 + c] * W1[(h * 8 + c) * 10 + j];
            #pragma unroll
            for (int i = 0; i < 5; i++) v += bf[i] * W1[(h * 8 + 3 + i) * 10 + j];
        }
        g_e[t] = v;
        return;
    }
    int u = t - E_SIZE;
    float v = 0.0f;
    if (u < 1280) {
        int h = u / 64; int o = u % 64;
        if (o < 36) {                       // W1f[h][c][j] = sum_i Wf[c][i]*W1[h][3+i][j]
            int c = o / 12; int j = o % 12;
            if (j < 10) {
                #pragma unroll
                for (int i = 0; i < 5; i++) v += Wf[c * 5 + i] * W1[(h * 8 + 3 + i) * 10 + j];
            }
        } else if (o < 48) {                // w2a = 0.505 * W2
            int j = o - 36; if (j < 10) v = 0.505f * W2[h * 10 + j];
        } else if (o < 60) {                // w2b = 0.495 * W2
            int j = o - 48; if (j < 10) v = 0.495f * W2[h * 10 + j];
        } else if (o == 60) {
            v = b2[h];
        } else if (o == 61) {
            v = Wo[h];
        }
    } else {
        v = bo[0];                          // u == 1280
    }
    g_w[u] = v;
}

__device__ __forceinline__ float fabs_bits(float x) {
    return __int_as_float(__float_as_int(x) & 0x7FFFFFFF);   // LOP3 on alu pipe
}

// ---------------------------------------------------------------------------
// Main: 1 sample/thread. E' from smem (indexed), all uniform weights from
// __constant__ (LDCU / uniform port -> zero L1 traffic, UR operands).
// ---------------------------------------------------------------------------
__global__ __launch_bounds__(256) void airfit_kernel(const int* __restrict__ e,
                                                     const float* __restrict__ f,
                                                     float* __restrict__ out, int B) {
    __shared__ __align__(16) float sE[E_SIZE];
    for (int i = threadIdx.x; i < E_SIZE; i += 256) sE[i] = g_e[i];
    __syncthreads();

    int s = blockIdx.x * 256 + threadIdx.x;
    if (s >= B) return;

    const float4* f4 = reinterpret_cast<const float4*>(f) + (size_t)s * 15;
    const int4*   e4 = reinterpret_cast<const int4*>(e)   + (size_t)s * 5;

    float res = c_w[1280];

    #pragma unroll
    for (int hg = 0; hg < 5; hg++) {
        float4 fA = f4[hg * 3 + 0];
        float4 fB = f4[hg * 3 + 1];
        float4 fC = f4[hg * 3 + 2];
        int4   ev = e4[hg];
        float g[12] = {fA.x, fA.y, fA.z, fA.w, fB.x, fB.y, fB.z, fB.w,
                       fC.x, fC.y, fC.z, fC.w};
        int idx[4] = {ev.x, ev.y, ev.z, ev.w};

        #pragma unroll
        for (int k = 0; k < 4; k++) {
            const int h = hg * 4 + k;
            const int wb = h * 64;                      // constant blob base (literal)

            // accumulator init = E'[h][e] row from smem
            const float* Er = &sE[(h * NUM_EX + idx[k]) * 12];
            float4 A0 = *reinterpret_cast<const float4*>(Er);
            float4 A1 = *reinterpret_cast<const float4*>(Er + 4);
            float2 A2 = *reinterpret_cast<const float2*>(Er + 8);
            float a[10] = {A0.x, A0.y, A0.z, A0.w, A1.x, A1.y, A1.z, A1.w, A2.x, A2.y};

            // + f(3) @ W1f(3x10), weights from constant (uniform port)
            #pragma unroll
            for (int c = 0; c < 3; c++) {
                float fv = g[k * 3 + c];
                #pragma unroll
                for (int j = 0; j < 10; j++)
                    a[j] = fmaf(fv, c_w[wb + c * 12 + j], a[j]);
            }

            // leaky folded: d = b2 + sum a_j*w2a_j + |a_j|*w2b_j
            float d = c_w[wb + 60];
            #pragma unroll
            for (int j = 0; j < 10; j++) {
                d = fmaf(a[j],          c_w[wb + 36 + j], d);
                d = fmaf(fabs_bits(a[j]), c_w[wb + 48 + j], d);
            }

            // softplus(d) = max(d,0) + log(1+exp(-|d|))
            float m = fmaxf(d, 0.0f);
            float z = __expf(-fabsf(d));
            float spv = m + __logf(1.0f + z);

            res = fmaf(spv, c_w[wb + 61], res);
        }
    }
    out[s] = res;
}

// ---------------------------------------------------------------------------
extern "C" void kernel_launch(void* const* d_in, const int* in_sizes, int n_in,
                              void* d_out, int out_size) {
    const int*   e   = (const int*)  d_in[0];
    const float* f   = (const float*)d_in[1];
    const float* emb = (const float*)d_in[2];
    const float* Wf  = (const float*)d_in[3];
    const float* bf  = (const float*)d_in[4];
    const float* W1  = (const float*)d_in[5];
    const float* b1  = (const float*)d_in[6];
    const float* W2  = (const float*)d_in[7];
    const float* b2  = (const float*)d_in[8];
    const float* Wo  = (const float*)d_in[9];
    const float* bo  = (const float*)d_in[10];
    float* out = (float*)d_out;
    int B = out_size;

    prep_kernel<<<(PREP_N + 255) / 256, 256>>>(emb, Wf, bf, W1, b1, W2, b2, Wo, bo);

    // push folded uniform weights into constant bank (D2D copy, graph-capturable)
    void* c_addr = nullptr;
    void* g_addr = nullptr;
    cudaGetSymbolAddress(&c_addr, c_w);
    cudaGetSymbolAddress(&g_addr, g_w);
    cudaMemcpyAsync(c_addr, g_addr, W_SIZE * sizeof(float), cudaMemcpyDeviceToDevice);

    airfit_kernel<<<(B + 255) / 256, 256>>>(e, f, out, B);
}

// round 6
// speedup vs baseline: 1.4013x; 1.1234x over previous
#include <cuda_runtime.h>

#define NHEADS  20
#define NUM_EX  13
#define TPB     128

// E' table (per-sample indexed): [h][idx][12] = 3120 floats (smem)
#define E_SIZE   3120
// Uniform weight blob -> __constant__: per head 64 floats:
//   [0..11] W1f c=0  [12..23] W1f c=1  [24..35] W1f c=2
//   [36..47] w2a=0.505*W2  [48..59] w2b=0.495*W2  [60] b2  [61] Wo
// plus [1280] = bo
#define W_SIZE   1281
#define PREP_N   (E_SIZE + W_SIZE)

__device__ float g_e[E_SIZE];
__device__ float g_w[W_SIZE + 3];
__constant__ float c_w[W_SIZE + 3];

// ---------------------------------------------------------------------------
// Prep: fold Wf/bf/emb/b1 into E'; fold leaky slopes into W2.
// ---------------------------------------------------------------------------
__global__ void prep_kernel(const float* __restrict__ emb, const float* __restrict__ Wf,
                            const float* __restrict__ bf,  const float* __restrict__ W1,
                            const float* __restrict__ b1,  const float* __restrict__ W2,
                            const float* __restrict__ b2,  const float* __restrict__ Wo,
                            const float* __restrict__ bo) {
    int t = blockIdx.x * blockDim.x + threadIdx.x;
    if (t >= PREP_N) return;
    if (t < E_SIZE) {
        int j = t % 12; int r = t / 12; int idx = r % NUM_EX; int h = r / NUM_EX;
        float v = 0.0f;
        if (j < 10) {
            v = b1[h * 10 + j];
            #pragma unroll
            for (int c = 0; c < 3; c++) v += emb[idx * 3 + c] * W1[(h * 8 + c) * 10 + j];
            #pragma unroll
            for (int i = 0; i < 5; i++) v += bf[i] * W1[(h * 8 + 3 + i) * 10 + j];
        }
        g_e[t] = v;
        return;
    }
    int u = t - E_SIZE;
    float v = 0.0f;
    if (u < 1280) {
        int h = u / 64; int o = u % 64;
        if (o < 36) {
            int c = o / 12; int j = o % 12;
            if (j < 10) {
                #pragma unroll
                for (int i = 0; i < 5; i++) v += Wf[c * 5 + i] * W1[(h * 8 + 3 + i) * 10 + j];
            }
        } else if (o < 48) {
            int j = o - 36; if (j < 10) v = 0.505f * W2[h * 10 + j];
        } else if (o < 60) {
            int j = o - 48; if (j < 10) v = 0.495f * W2[h * 10 + j];
        } else if (o == 60) {
            v = b2[h];
        } else if (o == 61) {
            v = Wo[h];
        }
    } else {
        v = bo[0];
    }
    g_w[u] = v;
}

__device__ __forceinline__ float fabs_bits(float x) {
    return __int_as_float(__float_as_int(x) & 0x7FFFFFFF);
}

// ---------------------------------------------------------------------------
// Main: f staged through smem with coalesced LDG (kills the 240B-stride
// wavefront blowup); E' in smem; uniform weights from __constant__.
// ---------------------------------------------------------------------------
__global__ __launch_bounds__(TPB) void airfit_kernel(const int* __restrict__ e,
                                                     const float* __restrict__ f,
                                                     float* __restrict__ out, int B) {
    __shared__ __align__(16) float4 sF[TPB * 15];   // 30720 B, row = 15 float4/sample
    __shared__ __align__(16) float  sE[E_SIZE];     // 12480 B

    // stage f tile, fully coalesced: 15 LDG.128 of consecutive lanes
    {
        const float4* fg = reinterpret_cast<const float4*>(f);
        size_t base = (size_t)blockIdx.x * TPB * 15;
        size_t lim  = (size_t)B * 15;
        #pragma unroll
        for (int k = 0; k < 15; k++) {
            size_t idx = base + k * TPB + threadIdx.x;
            if (idx < lim) sF[k * TPB + threadIdx.x] = fg[idx];
        }
    }
    for (int i = threadIdx.x; i < E_SIZE; i += TPB) sE[i] = g_e[i];
    __syncthreads();

    int s = blockIdx.x * TPB + threadIdx.x;
    if (s >= B) return;

    const int4*   e4  = reinterpret_cast<const int4*>(e) + (size_t)s * 5;
    const float4* myF = sF + threadIdx.x * 15;      // stride 15 f4 -> conflict-free

    float res = c_w[1280];

    #pragma unroll
    for (int hg = 0; hg < 5; hg++) {
        float4 fA = myF[hg * 3 + 0];
        float4 fB = myF[hg * 3 + 1];
        float4 fC = myF[hg * 3 + 2];
        int4   ev = __ldg(&e4[hg]);
        float g[12] = {fA.x, fA.y, fA.z, fA.w, fB.x, fB.y, fB.z, fB.w,
                       fC.x, fC.y, fC.z, fC.w};
        int idx[4] = {ev.x, ev.y, ev.z, ev.w};

        #pragma unroll
        for (int k = 0; k < 4; k++) {
            const int h = hg * 4 + k;
            const int wb = h * 64;

            const float* Er = &sE[(h * NUM_EX + idx[k]) * 12];
            float4 A0 = *reinterpret_cast<const float4*>(Er);
            float4 A1 = *reinterpret_cast<const float4*>(Er + 4);
            float2 A2 = *reinterpret_cast<const float2*>(Er + 8);
            float a[10] = {A0.x, A0.y, A0.z, A0.w, A1.x, A1.y, A1.z, A1.w, A2.x, A2.y};

            #pragma unroll
            for (int c = 0; c < 3; c++) {
                float fv = g[k * 3 + c];
                #pragma unroll
                for (int j = 0; j < 10; j++)
                    a[j] = fmaf(fv, c_w[wb + c * 12 + j], a[j]);
            }

            // leaky folded: d = b2 + sum a_j*(0.505 w2_j) + |a_j|*(0.495 w2_j)
            float d = c_w[wb + 60];
            #pragma unroll
            for (int j = 0; j < 10; j++) {
                d = fmaf(a[j],            c_w[wb + 36 + j], d);
                d = fmaf(fabs_bits(a[j]), c_w[wb + 48 + j], d);
            }

            // softplus(d) = max(d,0) + log(1+exp(-|d|))
            float m = fmaxf(d, 0.0f);
            float z = __expf(-fabsf(d));
            float spv = m + __logf(1.0f + z);

            res = fmaf(spv, c_w[wb + 61], res);
        }
    }
    out[s] = res;
}

// ---------------------------------------------------------------------------
extern "C" void kernel_launch(void* const* d_in, const int* in_sizes, int n_in,
                              void* d_out, int out_size) {
    const int*   e   = (const int*)  d_in[0];
    const float* f   = (const float*)d_in[1];
    const float* emb = (const float*)d_in[2];
    const float* Wf  = (const float*)d_in[3];
    const float* bf  = (const float*)d_in[4];
    const float* W1  = (const float*)d_in[5];
    const float* b1  = (const float*)d_in[6];
    const float* W2  = (const float*)d_in[7];
    const float* b2  = (const float*)d_in[8];
    const float* Wo  = (const float*)d_in[9];
    const float* bo  = (const float*)d_in[10];
    float* out = (float*)d_out;
    int B = out_size;

    prep_kernel<<<(PREP_N + 255) / 256, 256>>>(emb, Wf, bf, W1, b1, W2, b2, Wo, bo);

    void* c_addr = nullptr;
    void* g_addr = nullptr;
    cudaGetSymbolAddress(&c_addr, c_w);
    cudaGetSymbolAddress(&g_addr, g_w);
    cudaMemcpyAsync(c_addr, g_addr, W_SIZE * sizeof(float), cudaMemcpyDeviceToDevice);

    airfit_kernel<<<(B + TPB - 1) / TPB, TPB>>>(e, f, out, B);
}